// round 3
// baseline (speedup 1.0000x reference)
#include <cuda_runtime.h>

// SetEmbed: out[b] = (sum_{s<n_b} relu(X[b,s]@W1 + b1)) @ W2 + n_b*b2, then @ W3 + b3.
// Pool-after-relu refactor: per-element work is only the 64x16 GEMM.
// Packed f32x2 FMA over feature pairs halves FMA-pipe pressure vs scalar FFMA.

#define B_      2048
#define S_      512
#define NFT     64
#define K1      16
#define K2      12
#define NOUT    32
#define TS      128     // rows per smem tile
#define XPAD    66      // padded row stride (floats): 2-way max bank conflict on 8B reads
#define NTHREADS 128

__device__ __forceinline__ unsigned long long pack2(float lo, float hi) {
    unsigned long long r;
    asm("mov.b64 %0, {%1, %2};" : "=l"(r) : "f"(lo), "f"(hi));
    return r;
}
__device__ __forceinline__ void unpack2(unsigned long long v, float& lo, float& hi) {
    asm("mov.b64 {%0, %1}, %2;" : "=f"(lo), "=f"(hi) : "l"(v));
}
// d = a*b + d  (two independent fp32 FMAs, one instruction)
__device__ __forceinline__ void ffma2(unsigned long long& d, unsigned long long a,
                                      unsigned long long b) {
    asm("fma.rn.f32x2 %0, %1, %2, %3;" : "=l"(d) : "l"(a), "l"(b), "l"(d));
}

__global__ __launch_bounds__(NTHREADS) void setembed_kernel(
    const float* __restrict__ X, const int* __restrict__ setSizes,
    const float* __restrict__ W1, const float* __restrict__ b1,
    const float* __restrict__ W2, const float* __restrict__ b2,
    const float* __restrict__ W3, const float* __restrict__ b3,
    float* __restrict__ out)
{
    __shared__ __align__(16) float Xs[TS * XPAD];                 // 33792 B
    __shared__ __align__(16) unsigned long long w1p[(NFT/2)*K1];  // 4096 B  (w[2j][k], w[2j+1][k])
    __shared__ float red[4][K1];
    __shared__ float accs[K1];
    __shared__ float pooled[K2];

    const int b = blockIdx.x;
    const int t = threadIdx.x;
    const int n = setSizes[b];

    // Stage W1 as duplicated feature-pair packs: w1p[j*16+k] = (W1[2j][k], W1[2j+1][k])
    for (int idx = t; idx < (NFT/2)*K1; idx += NTHREADS) {
        int j = idx >> 4, k = idx & 15;
        w1p[idx] = pack2(W1[(2*j)*K1 + k], W1[(2*j+1)*K1 + k]);
    }

    float b1r[K1];
#pragma unroll
    for (int k = 0; k < K1; k++) b1r[k] = b1[k];

    float acc[K1];
#pragma unroll
    for (int k = 0; k < K1; k++) acc[k] = 0.f;

    const float4* Xg = reinterpret_cast<const float4*>(X + (size_t)b * S_ * NFT);

    for (int s0 = 0; s0 < n; s0 += TS) {
        const int cnt = min(TS, n - s0);
        // Coalesced stage: float4 LDG, scalar STS into padded rows.
        for (int idx = t; idx < cnt * 16; idx += NTHREADS) {
            int r = idx >> 4, c = idx & 15;
            float4 v = Xg[(s0 + r) * 16 + c];
            float* p = &Xs[r * XPAD + 4 * c];
            p[0] = v.x; p[1] = v.y; p[2] = v.z; p[3] = v.w;
        }
        __syncthreads();   // first iteration also covers w1p staging

        if (t < cnt) {
            unsigned long long h2[K1];
#pragma unroll
            for (int k = 0; k < K1; k++) h2[k] = 0ull;  // (0.f, 0.f)
            const int roff = t * XPAD;
#pragma unroll 8
            for (int j = 0; j < NFT/2; j++) {
                unsigned long long xv =
                    *reinterpret_cast<const unsigned long long*>(&Xs[roff + 2*j]);
                const ulonglong2* wr = reinterpret_cast<const ulonglong2*>(&w1p[j * K1]);
#pragma unroll
                for (int m = 0; m < 8; m++) {
                    ulonglong2 w = wr[m];        // LDS.128 broadcast: 2 packed weights
                    ffma2(h2[2*m],   xv, w.x);
                    ffma2(h2[2*m+1], xv, w.y);
                }
            }
#pragma unroll
            for (int k = 0; k < K1; k++) {
                float lo, hi; unpack2(h2[k], lo, hi);
                acc[k] += fmaxf(lo + hi + b1r[k], 0.f);   // relu(x@W1 + b1)
            }
        }
        __syncthreads();
    }

    // Block reduction of acc[16] across 128 threads.
#pragma unroll
    for (int k = 0; k < K1; k++)
#pragma unroll
        for (int off = 16; off; off >>= 1)
            acc[k] += __shfl_down_sync(0xffffffffu, acc[k], off);

    const int warp = t >> 5, lane = t & 31;
    if (lane == 0) {
#pragma unroll
        for (int k = 0; k < K1; k++) red[warp][k] = acc[k];
    }
    __syncthreads();
    if (t < K1) accs[t] = red[0][t] + red[1][t] + red[2][t] + red[3][t];
    __syncthreads();
    if (t < K2) {
        float p = (float)n * b2[t];       // mask-summed b2 contribution
#pragma unroll
        for (int k = 0; k < K1; k++) p += accs[k] * W2[k * K2 + t];
        pooled[t] = p;
    }
    __syncthreads();
    if (t < NOUT) {
        float o = b3[t];
#pragma unroll
        for (int m = 0; m < K2; m++) o += pooled[m] * W3[m * NOUT + t];
        out[(size_t)b * NOUT + t] = o;
    }
}

extern "C" void kernel_launch(void* const* d_in, const int* in_sizes, int n_in,
                              void* d_out, int out_size)
{
    const float* X   = (const float*)d_in[0];
    const int*   ss  = (const int*)  d_in[1];
    const float* W1  = (const float*)d_in[2];
    const float* b1  = (const float*)d_in[3];
    const float* W2  = (const float*)d_in[4];
    const float* b2  = (const float*)d_in[5];
    const float* W3  = (const float*)d_in[6];
    const float* b3  = (const float*)d_in[7];
    float* o = (float*)d_out;
    setembed_kernel<<<B_, NTHREADS>>>(X, ss, W1, b1, W2, b2, W3, b3, o);
}

// round 4
// speedup vs baseline: 1.3182x; 1.3182x over previous
#include <cuda_runtime.h>

// SetEmbed: out[b] = (sum_{s<n_b} relu(X[b,s]@W1 + b1)) @ W2 + n_b*b2, then @ W3 + b3.
// k-per-lane layout: W1 column lives in registers (zero weight LDS in hot loop),
// x tiles double-buffered into smem via cp.async.cg, packed f32x2 FMAs.

#define B_      2048
#define S_      512
#define NFT     64
#define K1      16
#define K2      12
#define NOUT    32
#define TSR     64      // rows per tile buffer
#define RSTRIDE 17      // float4 per smem row (68 floats): adjacent rows bank-disjoint
#define NTHREADS 128

__device__ __forceinline__ unsigned long long pack2(float lo, float hi) {
    unsigned long long r;
    asm("mov.b64 %0, {%1, %2};" : "=l"(r) : "f"(lo), "f"(hi));
    return r;
}
__device__ __forceinline__ void unpack2(unsigned long long v, float& lo, float& hi) {
    asm("mov.b64 {%0, %1}, %2;" : "=f"(lo), "=f"(hi) : "l"(v));
}
// d = a*b + d (two independent fp32 FMAs, one instruction)
__device__ __forceinline__ void ffma2(unsigned long long& d, unsigned long long a,
                                      unsigned long long b) {
    asm("fma.rn.f32x2 %0, %1, %2, %3;" : "=l"(d) : "l"(a), "l"(b), "l"(d));
}
__device__ __forceinline__ unsigned smem_u32(const void* p) {
    return (unsigned)__cvta_generic_to_shared(p);
}

__global__ __launch_bounds__(NTHREADS) void setembed_kernel(
    const float* __restrict__ X, const int* __restrict__ setSizes,
    const float* __restrict__ W1, const float* __restrict__ b1,
    const float* __restrict__ W2, const float* __restrict__ b2,
    const float* __restrict__ W3, const float* __restrict__ b3,
    float* __restrict__ out)
{
    __shared__ __align__(16) float4 Xs[2][TSR * RSTRIDE];  // 2 x 17408 B
    __shared__ float red[8][K1 + 1];
    __shared__ float accs[K1];
    __shared__ float pooled[K2];

    const int b    = blockIdx.x;
    const int t    = threadIdx.x;
    const int n    = setSizes[b];
    const int k    = t & 15;          // output index owned by this thread
    const int slot = t >> 4;          // 0..7  (row slot within an 8-row pass group)
    const int warp = t >> 5;
    const int half = (t >> 4) & 1;    // 0/1: which of the warp's two adjacent rows

    // W1 column k as 32 packed feature-pairs, register-resident for the whole kernel.
    unsigned long long w1r[NFT / 2];
#pragma unroll
    for (int j = 0; j < NFT / 2; j++)
        w1r[j] = pack2(W1[(2 * j) * K1 + k], W1[(2 * j + 1) * K1 + k]);
    const float b1k = b1[k];

    const float4* Xg = reinterpret_cast<const float4*>(X + (size_t)b * S_ * NFT);
    const int ntiles = (n + TSR - 1) / TSR;

    auto issue_tile = [&](int tile) {
        const int base = tile * TSR;
        const int cnt  = min(TSR, n - base);
        float4* dst = Xs[tile & 1];
#pragma unroll
        for (int m = 0; m < 8; m++) {
            int idx = t + m * NTHREADS;          // 0..1023 float4 slots
            int r = idx >> 4, c = idx & 15;
            if (r < cnt) {
                unsigned da = smem_u32(&dst[r * RSTRIDE + c]);
                const float4* sa = &Xg[(base + r) * 16 + c];
                asm volatile("cp.async.cg.shared.global [%0], [%1], 16;"
                             :: "r"(da), "l"(sa));
            }
        }
        asm volatile("cp.async.commit_group;");
    };

    float acc = 0.f;
    if (ntiles > 0) issue_tile(0);

    for (int tile = 0; tile < ntiles; tile++) {
        const int cnt = min(TSR, n - tile * TSR);
        if (tile + 1 < ntiles) {
            issue_tile(tile + 1);
            asm volatile("cp.async.wait_group 1;");
        } else {
            asm volatile("cp.async.wait_group 0;");
        }
        __syncthreads();

        const float4* buf = Xs[tile & 1];
#pragma unroll
        for (int pass = 0; pass < 8; pass++) {
            const int r0 = pass * 8 + warp * 2;       // warp-uniform first row
            if (r0 < cnt) {
                const int r = r0 + half;              // two adjacent rows per warp
                const ulonglong2* xr =
                    reinterpret_cast<const ulonglong2*>(&buf[r * RSTRIDE]);
                unsigned long long h2a = 0ull, h2b = 0ull;
#pragma unroll
                for (int j4 = 0; j4 < 16; j4++) {
                    ulonglong2 q = xr[j4];            // LDS.128: 4 features
                    ffma2(h2a, q.x, w1r[2 * j4]);     // weights from registers
                    ffma2(h2b, q.y, w1r[2 * j4 + 1]);
                }
                float a0, a1, c0, c1;
                unpack2(h2a, a0, a1);
                unpack2(h2b, c0, c1);
                float s = (a0 + a1) + (c0 + c1) + b1k;
                if (r < cnt) acc += fmaxf(s, 0.f);    // relu, masked tail row
            }
        }
        __syncthreads();
    }

    // Reduce acc over the 8 row-slots per k.
    red[slot][k] = acc;
    __syncthreads();
    if (t < K1) {
        float s = 0.f;
#pragma unroll
        for (int ss = 0; ss < 8; ss++) s += red[ss][t];
        accs[t] = s;
    }
    __syncthreads();
    if (t < K2) {
        float p = (float)n * b2[t];                   // mask-summed b2 contribution
#pragma unroll
        for (int kk = 0; kk < K1; kk++) p += accs[kk] * W2[kk * K2 + t];
        pooled[t] = p;
    }
    __syncthreads();
    if (t < NOUT) {
        float o = b3[t];
#pragma unroll
        for (int m = 0; m < K2; m++) o += pooled[m] * W3[m * NOUT + t];
        out[(size_t)b * NOUT + t] = o;
    }
}

extern "C" void kernel_launch(void* const* d_in, const int* in_sizes, int n_in,
                              void* d_out, int out_size)
{
    const float* X  = (const float*)d_in[0];
    const int*   ss = (const int*)  d_in[1];
    const float* W1 = (const float*)d_in[2];
    const float* b1 = (const float*)d_in[3];
    const float* W2 = (const float*)d_in[4];
    const float* b2 = (const float*)d_in[5];
    const float* W3 = (const float*)d_in[6];
    const float* b3 = (const float*)d_in[7];
    float* o = (float*)d_out;
    setembed_kernel<<<B_, NTHREADS>>>(X, ss, W1, b1, W2, b2, W3, b3, o);
}